// round 15
// baseline (speedup 1.0000x reference)
#include <cuda_runtime.h>
#include <cuda_fp16.h>
#include <cstdint>

// MeanShift: B=2, C=3, N=9216, 5 iters.
// w_ij = exp2( (2g*y_i).x_j - g||x_j||^2 - g||y_i||^2 ), g = 50/ln2.
// HMMA accumulation (m16n8k16 f16xf16+f32) + precomputed fp16 B-frag table.
// R15: points counting-sorted by 8^3 color cell; per-window fp16 bboxes;
// warp computes its 32-query bbox once and skips windows with box-to-box
// d2 > 26/g = 0.3605 -- those weights round to 0 in fp16 anyway (exact skip).
// 768 thr = 4 query-pairs x 6 j-splits, psum overlays points region.

#define NPTS 9216
#define NB 2
#define GG 72.13475204444817f
#define TPB 768
#define NJS 6
#define WINS_PER_JS 96
#define NWINT 576
#define NCELL 512

typedef unsigned long long u64;
typedef unsigned int u32;

__device__ float4 g_pts[NB * NPTS];     // sorted, pair-interleaved
__device__ float4 g_y[2][NB * NPTS];    // sorted order
__device__ __align__(16) unsigned char g_feat[NB * NWINT * 96];
__device__ uint4 g_wbb[NB * NWINT];     // packed h2 {min,-max} per dim
__device__ float4 g_sorted[NB * NPTS];  // {x,y,z,bn}
__device__ int g_perm[NB * NPTS];       // sorted pos -> original n
__device__ int g_hist[NB * NCELL];
__device__ int g_cnt[NB * NCELL];
__device__ int g_base[NB * NCELL];

// smem: pts [0,147456) | feat [147456,202752) | wbb [202752,211968)
#define SO_FEAT 147456
#define SO_WBB  202752
#define SMEMSZ  211968

static __device__ __forceinline__ u64 pk2(float a, float b) {
    u64 r; asm("mov.b64 %0,{%1,%2};" : "=l"(r) : "f"(a), "f"(b)); return r;
}
static __device__ __forceinline__ u64 fma2(u64 a, u64 b, u64 c) {
    u64 d; asm("fma.rn.f32x2 %0,%1,%2,%3;" : "=l"(d) : "l"(a), "l"(b), "l"(c)); return d;
}
static __device__ __forceinline__ u64 add2(u64 a, u64 b) {
    u64 d; asm("add.rn.f32x2 %0,%1,%2;" : "=l"(d) : "l"(a), "l"(b)); return d;
}
static __device__ __forceinline__ void lds2(u32 a, u64& x, u64& y) {
    asm volatile("ld.shared.v2.u64 {%0,%1},[%2];" : "=l"(x), "=l"(y) : "r"(a));
}
static __device__ __forceinline__ u32 lds32(u32 a) {
    u32 v; asm volatile("ld.shared.b32 %0,[%1];" : "=r"(v) : "r"(a)); return v;
}
static __device__ __forceinline__ u32 wgt2(u64 t) {
    u32 h;
    asm("{\n\t.reg .f32 lo,hi;\n\tmov.b64 {lo,hi},%1;\n\t"
        "cvt.rn.f16x2.f32 %0,hi,lo;\n\tex2.approx.f16x2 %0,%0;\n\t}" : "=r"(h) : "l"(t));
    return h;
}
static __device__ __forceinline__ void mma16816(
    float& c0, float& c1, float& c2, float& c3,
    u32 a0, u32 a1, u32 a2, u32 a3, u32 b0, u32 b1) {
    asm volatile("mma.sync.aligned.m16n8k16.row.col.f32.f16.f16.f32 "
        "{%0,%1,%2,%3}, {%4,%5,%6,%7}, {%8,%9}, {%0,%1,%2,%3};"
        : "+f"(c0), "+f"(c1), "+f"(c2), "+f"(c3)
        : "r"(a0), "r"(a1), "r"(a2), "r"(a3), "r"(b0), "r"(b1));
}

static __device__ __forceinline__ int cellkey(float px, float py, float pz) {
    int ix = (int)(px * 8.0f); ix = ix < 0 ? 0 : (ix > 7 ? 7 : ix);
    int iy = (int)(py * 8.0f); iy = iy < 0 ? 0 : (iy > 7 ? 7 : iy);
    int iz = (int)(pz * 8.0f); iz = iz < 0 ? 0 : (iz > 7 ? 7 : iz);
    return (ix << 6) | (iy << 3) | iz;
}

__global__ void pz_kernel() {
    int i = blockIdx.x * blockDim.x + threadIdx.x;
    if (i < NB * NCELL) { g_hist[i] = 0; g_cnt[i] = 0; }
}

__global__ void p0_kernel(const float* __restrict__ x) {
    int idx = blockIdx.x * blockDim.x + threadIdx.x;
    if (idx >= NB * NPTS) return;
    int b = idx / NPTS, n = idx - b * NPTS;
    float px = x[(b * 3 + 0) * NPTS + n];
    float py = x[(b * 3 + 1) * NPTS + n];
    float pz = x[(b * 3 + 2) * NPTS + n];
    atomicAdd(&g_hist[b * NCELL + cellkey(px, py, pz)], 1);
}

__global__ void p1_kernel() {   // exclusive scan per batch, 512 threads
    __shared__ int s[NCELL];
    int b = blockIdx.x, t = threadIdx.x;
    int h = g_hist[b * NCELL + t];
    s[t] = h;
    __syncthreads();
    for (int off = 1; off < NCELL; off <<= 1) {
        int v = (t >= off) ? s[t - off] : 0;
        __syncthreads();
        s[t] += v;
        __syncthreads();
    }
    g_base[b * NCELL + t] = s[t] - h;
}

__global__ void p2_kernel(const float* __restrict__ x) {
    int idx = blockIdx.x * blockDim.x + threadIdx.x;
    if (idx >= NB * NPTS) return;
    int b = idx / NPTS, n = idx - b * NPTS;
    float px = x[(b * 3 + 0) * NPTS + n];
    float py = x[(b * 3 + 1) * NPTS + n];
    float pz = x[(b * 3 + 2) * NPTS + n];
    int key = cellkey(px, py, pz);
    int dst = g_base[b * NCELL + key] + atomicAdd(&g_cnt[b * NCELL + key], 1);
    float bn = -GG * (px * px + py * py + pz * pz);
    g_sorted[b * NPTS + dst] = make_float4(px, py, pz, bn);
    g_perm[b * NPTS + dst] = n;
}

__global__ void p3_kernel() {
    int idx = blockIdx.x * blockDim.x + threadIdx.x;
    if (idx >= NB * NPTS) return;
    int b = idx / NPTS, m = idx - b * NPTS;
    float4 s = g_sorted[b * NPTS + m];
    int jp = m >> 1, l = m & 1;
    float* base = (float*)&g_pts[b * NPTS + 2 * jp];
    base[0 + l] = s.x; base[2 + l] = s.y; base[4 + l] = s.z; base[6 + l] = s.w;
    g_y[0][b * NPTS + m] = make_float4(s.x, s.y, s.z, 0.f);
    int w = m >> 4, i = m & 15;
    unsigned char* fb = g_feat + ((size_t)(b * NWINT + w)) * 96 + 2 * i;
    *(__half*)(fb + 0)  = __float2half(s.x);
    *(__half*)(fb + 32) = __float2half(s.y);
    *(__half*)(fb + 64) = __float2half(s.z);
}

__global__ void p4_kernel() {   // per-window bbox, packed h2 {min, -max}
    int idx = blockIdx.x * blockDim.x + threadIdx.x;
    if (idx >= NB * NWINT) return;
    int b = idx / NWINT, w = idx - b * NWINT;
    float mnx = 1e30f, mny = 1e30f, mnz = 1e30f;
    float mxx = -1e30f, mxy = -1e30f, mxz = -1e30f;
    for (int k = 0; k < 16; k++) {
        float4 s = g_sorted[b * NPTS + w * 16 + k];
        mnx = fminf(mnx, s.x); mxx = fmaxf(mxx, s.x);
        mny = fminf(mny, s.y); mxy = fmaxf(mxy, s.y);
        mnz = fminf(mnz, s.z); mxz = fmaxf(mxz, s.z);
    }
    u32 bx = (u32)__half_as_ushort(__float2half_rd(mnx))
           | ((u32)__half_as_ushort(__float2half_rd(-mxx)) << 16);
    u32 by = (u32)__half_as_ushort(__float2half_rd(mny))
           | ((u32)__half_as_ushort(__float2half_rd(-mxy)) << 16);
    u32 bz = (u32)__half_as_ushort(__float2half_rd(mnz))
           | ((u32)__half_as_ushort(__float2half_rd(-mxz)) << 16);
    g_wbb[b * NWINT + w] = make_uint4(bx, by, bz, 0u);
}

__global__ __launch_bounds__(TPB, 1) void iter_kernel(int src, int dst, float* __restrict__ out) {
    extern __shared__ __align__(16) unsigned char smem[];
    const int tid = threadIdx.x, wid = tid >> 5, lane = tid & 31;
    const int g = lane >> 2, t = lane & 3;
    const int b = blockIdx.y, tile = blockIdx.x;
    u32 sb = (u32)__cvta_generic_to_shared(smem);

    {   // stage points + feat + bboxes
        const float4* gp = g_pts + b * NPTS;
        float4* sp = (float4*)smem;
        for (int i = tid; i < NPTS; i += TPB) sp[i] = gp[i];
        const float4* gf = (const float4*)(g_feat + (size_t)b * NWINT * 96);
        float4* sf = (float4*)(smem + SO_FEAT);
        for (int i = tid; i < NWINT * 6; i += TPB) sf[i] = gf[i];
        const uint4* gw = g_wbb + b * NWINT;
        uint4* sw = (uint4*)(smem + SO_WBB);
        for (int i = tid; i < NWINT; i += TPB) sw[i] = gw[i];
    }
    __syncthreads();

    const int qp = wid & 3;
    const int js = wid >> 2;
    const int qA0 = qp * 32 + g;
    const int qA1 = qA0 + 8;
    const int qB0 = qA0 + 16;
    const int qB1 = qA0 + 24;

    const float tg = 2.0f * GG;
    u64 axA0, ayA0, azA0, ppA0, axA1, ayA1, azA1, ppA1;
    u64 axB0, ayB0, azB0, ppB0, axB1, ayB1, azB1, ppB1;
    float4 y0 = g_y[src][b * NPTS + tile * 128 + qA0];
    float4 y1 = g_y[src][b * NPTS + tile * 128 + qA1];
    float4 y2 = g_y[src][b * NPTS + tile * 128 + qB0];
    float4 y3 = g_y[src][b * NPTS + tile * 128 + qB1];
    {
        float p;
        axA0 = pk2(tg * y0.x, tg * y0.x); ayA0 = pk2(tg * y0.y, tg * y0.y);
        azA0 = pk2(tg * y0.z, tg * y0.z);
        p = -GG * (y0.x * y0.x + y0.y * y0.y + y0.z * y0.z); ppA0 = pk2(p, p);
        axA1 = pk2(tg * y1.x, tg * y1.x); ayA1 = pk2(tg * y1.y, tg * y1.y);
        azA1 = pk2(tg * y1.z, tg * y1.z);
        p = -GG * (y1.x * y1.x + y1.y * y1.y + y1.z * y1.z); ppA1 = pk2(p, p);
        axB0 = pk2(tg * y2.x, tg * y2.x); ayB0 = pk2(tg * y2.y, tg * y2.y);
        azB0 = pk2(tg * y2.z, tg * y2.z);
        p = -GG * (y2.x * y2.x + y2.y * y2.y + y2.z * y2.z); ppB0 = pk2(p, p);
        axB1 = pk2(tg * y3.x, tg * y3.x); ayB1 = pk2(tg * y3.y, tg * y3.y);
        azB1 = pk2(tg * y3.z, tg * y3.z);
        p = -GG * (y3.x * y3.x + y3.y * y3.y + y3.z * y3.z); ppB1 = pk2(p, p);
    }

    // Warp query bbox (all 32 queries = union over g of this thread's 4).
    u32 qvx, qvy, qvz;
    {
        float mnx = fminf(fminf(y0.x, y1.x), fminf(y2.x, y3.x));
        float mxx = fmaxf(fmaxf(y0.x, y1.x), fmaxf(y2.x, y3.x));
        float mny = fminf(fminf(y0.y, y1.y), fminf(y2.y, y3.y));
        float mxy = fmaxf(fmaxf(y0.y, y1.y), fmaxf(y2.y, y3.y));
        float mnz = fminf(fminf(y0.z, y1.z), fminf(y2.z, y3.z));
        float mxz = fmaxf(fmaxf(y0.z, y1.z), fmaxf(y2.z, y3.z));
        for (int o = 16; o; o >>= 1) {
            mnx = fminf(mnx, __shfl_xor_sync(0xffffffffu, mnx, o));
            mxx = fmaxf(mxx, __shfl_xor_sync(0xffffffffu, mxx, o));
            mny = fminf(mny, __shfl_xor_sync(0xffffffffu, mny, o));
            mxy = fmaxf(mxy, __shfl_xor_sync(0xffffffffu, mxy, o));
            mnz = fminf(mnz, __shfl_xor_sync(0xffffffffu, mnz, o));
            mxz = fmaxf(mxz, __shfl_xor_sync(0xffffffffu, mxz, o));
        }
        qvx = (u32)__half_as_ushort(__float2half_ru(mxx))
            | ((u32)__half_as_ushort(__float2half_ru(-mnx)) << 16);
        qvy = (u32)__half_as_ushort(__float2half_ru(mxy))
            | ((u32)__half_as_ushort(__float2half_ru(-mny)) << 16);
        qvz = (u32)__half_as_ushort(__float2half_ru(mxz))
            | ((u32)__half_as_ushort(__float2half_ru(-mnz)) << 16);
    }

    const u32 mand = (g < 3) ? 0xFFFFFFFFu : 0u;
    const u32 mor  = (g == 3) ? 0x3C003C00u : 0u;
    const int gm2  = (g < 3) ? g : 0;

    float cA0 = 0.f, cA1 = 0.f, cA2 = 0.f, cA3 = 0.f;
    float cB0 = 0.f, cB1 = 0.f, cB2 = 0.f, cB3 = 0.f;

    u32 base = sb + (u32)(js * WINS_PER_JS) * 256u + 32u * (u32)t;
    u32 fb = sb + SO_FEAT + (u32)(js * WINS_PER_JS) * 96u + (u32)(gm2 * 32 + t * 4);
    u32 wb = sb + SO_WBB + (u32)(js * WINS_PER_JS) * 16u;

    for (int w = 0; w < WINS_PER_JS; w++, base += 256u, fb += 96u, wb += 16u) {
        // box-to-box d2 test in f16x2: gaps = max2(bb - qv, 0); d2 = sum gap^2.
        u32 bx = lds32(wb), by = lds32(wb + 4), bz = lds32(wb + 8);
        u32 gx, gy, gz, acc;
        asm("sub.f16x2 %0,%1,%2;" : "=r"(gx) : "r"(bx), "r"(qvx));
        asm("sub.f16x2 %0,%1,%2;" : "=r"(gy) : "r"(by), "r"(qvy));
        asm("sub.f16x2 %0,%1,%2;" : "=r"(gz) : "r"(bz), "r"(qvz));
        asm("max.f16x2 %0,%1,%2;" : "=r"(gx) : "r"(gx), "r"(0u));
        asm("max.f16x2 %0,%1,%2;" : "=r"(gy) : "r"(gy), "r"(0u));
        asm("max.f16x2 %0,%1,%2;" : "=r"(gz) : "r"(gz), "r"(0u));
        asm("mul.f16x2 %0,%1,%1;" : "=r"(acc) : "r"(gz));
        asm("fma.rn.f16x2 %0,%1,%1,%2;" : "=r"(acc) : "r"(gy), "r"(acc));
        asm("fma.rn.f16x2 %0,%1,%1,%2;" : "=r"(acc) : "r"(gx), "r"(acc));
        float dlo, dhi;
        asm("{\n\t.reg .b16 l,h;\n\tmov.b32 {l,h},%2;\n\t"
            "cvt.f32.f16 %0,l;\n\tcvt.f32.f16 %1,h;\n\t}"
            : "=f"(dlo), "=f"(dhi) : "r"(acc));
        if (dlo + dhi < 0.375f) {
            u64 xx0, yy0, zz0, bb0, xx1, yy1, zz1, bb1;
            lds2(base, xx0, yy0);
            lds2(base + 16u, zz0, bb0);
            lds2(base + 128u, xx1, yy1);
            lds2(base + 144u, zz1, bb1);

            u64 tA00 = fma2(axA0, xx0, fma2(ayA0, yy0, fma2(azA0, zz0, add2(bb0, ppA0))));
            u64 tA10 = fma2(axA1, xx0, fma2(ayA1, yy0, fma2(azA1, zz0, add2(bb0, ppA1))));
            u64 tB00 = fma2(axB0, xx0, fma2(ayB0, yy0, fma2(azB0, zz0, add2(bb0, ppB0))));
            u64 tB10 = fma2(axB1, xx0, fma2(ayB1, yy0, fma2(azB1, zz0, add2(bb0, ppB1))));
            u64 tA01 = fma2(axA0, xx1, fma2(ayA0, yy1, fma2(azA0, zz1, add2(bb1, ppA0))));
            u64 tA11 = fma2(axA1, xx1, fma2(ayA1, yy1, fma2(azA1, zz1, add2(bb1, ppA1))));
            u64 tB01 = fma2(axB0, xx1, fma2(ayB0, yy1, fma2(azB0, zz1, add2(bb1, ppB0))));
            u64 tB11 = fma2(axB1, xx1, fma2(ayB1, yy1, fma2(azB1, zz1, add2(bb1, ppB1))));

            u32 f0 = lds32(fb);
            u32 f1 = lds32(fb + 16u);
            u32 b0 = (f0 & mand) | mor;
            u32 b1 = (f1 & mand) | mor;

            mma16816(cA0, cA1, cA2, cA3,
                     wgt2(tA00), wgt2(tA10), wgt2(tA01), wgt2(tA11), b0, b1);
            mma16816(cB0, cB1, cB2, cB3,
                     wgt2(tB00), wgt2(tB10), wgt2(tB01), wgt2(tB11), b0, b1);
        }
    }

    __syncthreads();   // points region is dead; psum overlays it

    float* ps = (float*)smem;
    if (t == 0) {
        ps[(js * 128 + qA0) * 4 + 0] = cA0; ps[(js * 128 + qA0) * 4 + 1] = cA1;
        ps[(js * 128 + qA1) * 4 + 0] = cA2; ps[(js * 128 + qA1) * 4 + 1] = cA3;
        ps[(js * 128 + qB0) * 4 + 0] = cB0; ps[(js * 128 + qB0) * 4 + 1] = cB1;
        ps[(js * 128 + qB1) * 4 + 0] = cB2; ps[(js * 128 + qB1) * 4 + 1] = cB3;
    } else if (t == 1) {
        ps[(js * 128 + qA0) * 4 + 2] = cA0; ps[(js * 128 + qA0) * 4 + 3] = cA1;
        ps[(js * 128 + qA1) * 4 + 2] = cA2; ps[(js * 128 + qA1) * 4 + 3] = cA3;
        ps[(js * 128 + qB0) * 4 + 2] = cB0; ps[(js * 128 + qB0) * 4 + 3] = cB1;
        ps[(js * 128 + qB1) * 4 + 2] = cB2; ps[(js * 128 + qB1) * 4 + 3] = cB3;
    }
    __syncthreads();

    if (tid < 128) {
        float4* pv = (float4*)smem;
        float4 a = pv[tid];
        #pragma unroll
        for (int k = 1; k < NJS; k++) {
            float4 s = pv[k * 128 + tid];
            a.x += s.x; a.y += s.y; a.z += s.z; a.w += s.w;
        }
        float inv = __fdividef(1.0f, a.w);
        float nx = a.x * inv, ny = a.y * inv, nz = a.z * inv;
        int qi = tile * 128 + tid;
        g_y[dst][b * NPTS + qi] = make_float4(nx, ny, nz, 0.f);
        if (out) {
            int orig = g_perm[b * NPTS + qi];
            out[(b * 3 + 0) * NPTS + orig] = nx;
            out[(b * 3 + 1) * NPTS + orig] = ny;
            out[(b * 3 + 2) * NPTS + orig] = nz;
        }
    }
}

extern "C" void kernel_launch(void* const* d_in, const int* in_sizes, int n_in,
                              void* d_out, int out_size) {
    const float* x = (const float*)d_in[0];
    float* out = (float*)d_out;

    cudaFuncSetAttribute(iter_kernel, cudaFuncAttributeMaxDynamicSharedMemorySize, SMEMSZ);

    pz_kernel<<<(NB * NCELL + 255) / 256, 256>>>();
    p0_kernel<<<(NB * NPTS + 255) / 256, 256>>>(x);
    p1_kernel<<<NB, NCELL>>>();
    p2_kernel<<<(NB * NPTS + 255) / 256, 256>>>(x);
    p3_kernel<<<(NB * NPTS + 255) / 256, 256>>>();
    p4_kernel<<<(NB * NWINT + 255) / 256, 256>>>();

    dim3 grid(72, NB);
    for (int it = 0; it < 5; it++) {
        iter_kernel<<<grid, TPB, SMEMSZ>>>(it & 1, (it & 1) ^ 1, (it == 4) ? out : nullptr);
    }
}